// round 11
// baseline (speedup 1.0000x reference)
#include <cuda_runtime.h>
#include <cstdint>

// x: [16, 64, 128, 128] (B, C, H, W), HX = HY = 64.
// Pass 1: 2048 sequences (b,h), T=128 along w.
// Pass 2: 2048 sequences (b,w), T=128 along h.

using ull = unsigned long long;

__device__ float g_pre[2048 * 128 * 64];   // [seq][t][j]
__device__ float g_mid[2048 * 128 * 64];   // [(b,h)][w][j]  natural scan_x output
__device__ float g_WTx[64 * 64];           // Wih_x^T: [c][j]
__device__ ull   g_Wpy[32 * 64];           // Wy j-pairs: [jp][j2] = (Wy[j2][2jp], Wy[j2][2jp+1])
__device__ ull   g_bsdx[64];               // dup'd bias sum x
__device__ float g_bsy[64];                // plain bias sum y

__device__ __forceinline__ ull ffma2(ull a, ull b, ull c) {
    ull d;
    asm("fma.rn.f32x2 %0, %1, %2, %3;" : "=l"(d) : "l"(a), "l"(b), "l"(c));
    return d;
}
__device__ __forceinline__ ull addf2(ull a, ull b) {
    ull d;
    asm("add.rn.f32x2 %0, %1, %2;" : "=l"(d) : "l"(a), "l"(b));
    return d;
}
__device__ __forceinline__ ull dup2(float x) {
    ull d;
    asm("mov.b64 %0, {%1, %1};" : "=l"(d) : "r"(__float_as_uint(x)));
    return d;
}
__device__ __forceinline__ float lo_f(ull v) { return __uint_as_float((unsigned)(v & 0xffffffffull)); }
__device__ __forceinline__ float hi_f(ull v) { return __uint_as_float((unsigned)(v >> 32)); }
__device__ __forceinline__ float tanh_fast(float x) {
    float r;
    asm("tanh.approx.f32 %0, %1;" : "=f"(r) : "f"(x));
    return r;
}
__device__ __forceinline__ void cp_async16(uint32_t dst, const void* src) {
    asm volatile("cp.async.cg.shared.global [%0], [%1], 16;" :: "r"(dst), "l"(src));
}
#define CP_COMMIT() asm volatile("cp.async.commit_group;")
#define CP_WAIT(n)  asm volatile("cp.async.wait_group %0;" :: "n"(n))

// ---------------------------------------------------------------------------
// Prep.
// ---------------------------------------------------------------------------
__global__ void prep_kernel(const float* __restrict__ Wih_x,
                            const float* __restrict__ Wih_y,
                            const float* __restrict__ bih_x,
                            const float* __restrict__ bhh_x,
                            const float* __restrict__ bih_y,
                            const float* __restrict__ bhh_y) {
    int t = threadIdx.x;
    for (int e = t; e < 4096; e += 256) {
        int c = e >> 6, j = e & 63;
        g_WTx[c * 64 + j] = Wih_x[j * 64 + c];
    }
    for (int e = t; e < 2048; e += 256) {
        int jp = e >> 6, j2 = e & 63;
        g_Wpy[e] = *(const ull*)&Wih_y[j2 * 64 + 2 * jp];
    }
    if (t < 64) {
        g_bsdx[t] = dup2(bih_x[t] + bhh_x[t]);
        g_bsy[t]  = bih_y[t] + bhh_y[t];
    }
}

// ---------------------------------------------------------------------------
// proj_x: pre[(b,h)][w][j] = bias[j] + sum_c x[b][c][h][w] * Wx[j][c]
// (r8 structure: c-major input tile, broadcast X, conflict-free W sweep)
// ---------------------------------------------------------------------------
__global__ __launch_bounds__(256) void proj_x_kernel(const float* __restrict__ src) {
    __shared__ float in_sh[64][128];   // [c][pos]  32KB
    __shared__ float W_sh[64][64];     // [c][j]    16KB

    int tid = threadIdx.x;
    int row = blockIdx.x;
    int b = row >> 7, h = row & 127;
    const float* base = src + (size_t)b * 1048576 + (size_t)h * 128;

    uint32_t shW = (uint32_t)__cvta_generic_to_shared(&W_sh[0][0]);
    uint32_t shI = (uint32_t)__cvta_generic_to_shared(&in_sh[0][0]);

    {
        #pragma unroll
        for (int i = 0; i < 4; i++) {
            int e = tid + i * 256;               // 0..1023
            cp_async16(shW + e * 16, g_WTx + e * 4);
        }
        #pragma unroll
        for (int i = 0; i < 8; i++) {
            int e = tid + i * 256;               // 0..2047, 32 granules/row
            int c = e >> 5, g4 = e & 31;
            cp_async16(shI + e * 16, base + (size_t)c * 16384 + g4 * 4);
        }
        CP_COMMIT();
        CP_WAIT(0);
        __syncthreads();
    }

    int pt = tid >> 4;    // position group of 8 (broadcast X)
    int jt = tid & 15;    // output group of 4 (conflict-free W)

    const ull* bd = g_bsdx + jt * 4;
    ull a[4][4];
    #pragma unroll
    for (int o = 0; o < 4; o++) {
        ull bv = bd[o];
        a[0][o] = bv; a[1][o] = bv; a[2][o] = bv; a[3][o] = bv;
    }

    #pragma unroll 8
    for (int c = 0; c < 64; c++) {
        ulonglong2 X0 = *(const ulonglong2*)&in_sh[c][pt * 8];
        ulonglong2 X1 = *(const ulonglong2*)&in_sh[c][pt * 8 + 4];
        float4 wv = *(const float4*)&W_sh[c][jt * 4];
        ull w0 = dup2(wv.x), w1 = dup2(wv.y), w2 = dup2(wv.z), w3 = dup2(wv.w);
        a[0][0] = ffma2(X0.x, w0, a[0][0]);  a[1][0] = ffma2(X0.y, w0, a[1][0]);
        a[2][0] = ffma2(X1.x, w0, a[2][0]);  a[3][0] = ffma2(X1.y, w0, a[3][0]);
        a[0][1] = ffma2(X0.x, w1, a[0][1]);  a[1][1] = ffma2(X0.y, w1, a[1][1]);
        a[2][1] = ffma2(X1.x, w1, a[2][1]);  a[3][1] = ffma2(X1.y, w1, a[3][1]);
        a[0][2] = ffma2(X0.x, w2, a[0][2]);  a[1][2] = ffma2(X0.y, w2, a[1][2]);
        a[2][2] = ffma2(X1.x, w2, a[2][2]);  a[3][2] = ffma2(X1.y, w2, a[3][2]);
        a[0][3] = ffma2(X0.x, w3, a[0][3]);  a[1][3] = ffma2(X0.y, w3, a[1][3]);
        a[2][3] = ffma2(X1.x, w3, a[2][3]);  a[3][3] = ffma2(X1.y, w3, a[3][3]);
    }

    float* dst = g_pre + (size_t)row * 8192 + (pt * 8) * 64 + jt * 4;
    #pragma unroll
    for (int pp = 0; pp < 4; pp++) {
        float4 o;
        o = make_float4(lo_f(a[pp][0]), lo_f(a[pp][1]), lo_f(a[pp][2]), lo_f(a[pp][3]));
        *(float4*)(dst + (pp * 2 + 0) * 64) = o;
        o = make_float4(hi_f(a[pp][0]), hi_f(a[pp][1]), hi_f(a[pp][2]), hi_f(a[pp][3]));
        *(float4*)(dst + (pp * 2 + 1) * 64) = o;
    }
}

// ---------------------------------------------------------------------------
// proj_y: pre[(b,w)][h][j2] = bias[j2] + sum_j mid[(b,h)][w][j] * Wy[j2][j]
// Input staged pos-major in_sh[h][j] (contiguous 256B runs from natural g_mid).
// FFMA2 pairs over the reduction dim j via prep-packed Wp[jp][j2] ull pairs:
// per jp: 2 LDS.64 (broadcast) + 4 LDS.128 (conflict-free) + 16 FFMA2, no dups.
// Two 64-pos halves. Thread tile: 2 pos x 8 j2.
// ---------------------------------------------------------------------------
__global__ __launch_bounds__(256) void proj_y_kernel() {
    __shared__ float in_sh[64][68];    // [pos-local h][j], pad 68: aligned+conflict-free
    __shared__ ull   Wp_sh[32][64];    // [jp][j2] 16KB

    int tid = threadIdx.x;
    int row = blockIdx.x;              // b*128 + w
    int b = row >> 7, w = row & 127;

    const float* mid_base = g_mid + (size_t)b * 131072 * 8 + (size_t)w * 64;  // b*1048576

    uint32_t shW = (uint32_t)__cvta_generic_to_shared(&Wp_sh[0][0]);
    uint32_t shI = (uint32_t)__cvta_generic_to_shared(&in_sh[0][0]);

    // Stage Wp (1024 granules) + half 0 (1024 granules): 4+4 per thread.
    {
        #pragma unroll
        for (int i = 0; i < 4; i++) {
            int e = tid + i * 256;
            cp_async16(shW + e * 16, g_Wpy + e * 2);
        }
        #pragma unroll
        for (int i = 0; i < 4; i++) {
            int e = tid + i * 256;               // 0..1023: 64 h-rows x 16 granules
            int hl = e >> 4, g4 = e & 15;
            cp_async16(shI + (hl * 68 + g4 * 4) * 4,
                       mid_base + (size_t)hl * 8192 + g4 * 4);
        }
        CP_COMMIT();
        CP_WAIT(0);
        __syncthreads();
    }

    int pg = tid >> 3;     // 0..31 -> positions pg*2, pg*2+1
    int jg = tid & 7;      // 0..7  -> outputs jg*8 .. jg*8+7

    float bias[8];
    {
        float4 b0 = *(const float4*)&g_bsy[jg * 8];
        float4 b1 = *(const float4*)&g_bsy[jg * 8 + 4];
        bias[0] = b0.x; bias[1] = b0.y; bias[2] = b0.z; bias[3] = b0.w;
        bias[4] = b1.x; bias[5] = b1.y; bias[6] = b1.z; bias[7] = b1.w;
    }

    #pragma unroll
    for (int half = 0; half < 2; half++) {
        ull a0[8], a1[8];                       // pair-partials, [j2] for pos0, pos1
        #pragma unroll
        for (int o = 0; o < 8; o++) { a0[o] = 0; a1[o] = 0; }

        #pragma unroll 8
        for (int jp = 0; jp < 32; jp++) {
            ull X0 = *(const ull*)&in_sh[pg * 2 + 0][jp * 2];
            ull X1 = *(const ull*)&in_sh[pg * 2 + 1][jp * 2];
            ulonglong2 wA = *(const ulonglong2*)&Wp_sh[jp][jg * 8];
            ulonglong2 wB = *(const ulonglong2*)&Wp_sh[jp][jg * 8 + 2];
            ulonglong2 wC = *(const ulonglong2*)&Wp_sh[jp][jg * 8 + 4];
            ulonglong2 wD = *(const ulonglong2*)&Wp_sh[jp][jg * 8 + 6];
            a0[0] = ffma2(X0, wA.x, a0[0]);  a1[0] = ffma2(X1, wA.x, a1[0]);
            a0[1] = ffma2(X0, wA.y, a0[1]);  a1[1] = ffma2(X1, wA.y, a1[1]);
            a0[2] = ffma2(X0, wB.x, a0[2]);  a1[2] = ffma2(X1, wB.x, a1[2]);
            a0[3] = ffma2(X0, wB.y, a0[3]);  a1[3] = ffma2(X1, wB.y, a1[3]);
            a0[4] = ffma2(X0, wC.x, a0[4]);  a1[4] = ffma2(X1, wC.x, a1[4]);
            a0[5] = ffma2(X0, wC.y, a0[5]);  a1[5] = ffma2(X1, wC.y, a1[5]);
            a0[6] = ffma2(X0, wD.x, a0[6]);  a1[6] = ffma2(X1, wD.x, a1[6]);
            a0[7] = ffma2(X0, wD.y, a0[7]);  a1[7] = ffma2(X1, wD.y, a1[7]);
        }

        __syncthreads();                        // done reading in_sh
        if (half == 0) {
            #pragma unroll
            for (int i = 0; i < 4; i++) {
                int e = tid + i * 256;
                int hl = e >> 4, g4 = e & 15;
                cp_async16(shI + (hl * 68 + g4 * 4) * 4,
                           mid_base + (size_t)(64 + hl) * 8192 + g4 * 4);
            }
            CP_COMMIT();
        }

        // Store: 8 consecutive j2 per position (two float4 per pos).
        float* dst = g_pre + (size_t)row * 8192 + (half * 64 + pg * 2) * 64 + jg * 8;
        float4 o;
        o = make_float4(bias[0] + lo_f(a0[0]) + hi_f(a0[0]),
                        bias[1] + lo_f(a0[1]) + hi_f(a0[1]),
                        bias[2] + lo_f(a0[2]) + hi_f(a0[2]),
                        bias[3] + lo_f(a0[3]) + hi_f(a0[3]));
        *(float4*)(dst + 0) = o;
        o = make_float4(bias[4] + lo_f(a0[4]) + hi_f(a0[4]),
                        bias[5] + lo_f(a0[5]) + hi_f(a0[5]),
                        bias[6] + lo_f(a0[6]) + hi_f(a0[6]),
                        bias[7] + lo_f(a0[7]) + hi_f(a0[7]));
        *(float4*)(dst + 4) = o;
        o = make_float4(bias[0] + lo_f(a1[0]) + hi_f(a1[0]),
                        bias[1] + lo_f(a1[1]) + hi_f(a1[1]),
                        bias[2] + lo_f(a1[2]) + hi_f(a1[2]),
                        bias[3] + lo_f(a1[3]) + hi_f(a1[3]));
        *(float4*)(dst + 64) = o;
        o = make_float4(bias[4] + lo_f(a1[4]) + hi_f(a1[4]),
                        bias[5] + lo_f(a1[5]) + hi_f(a1[5]),
                        bias[6] + lo_f(a1[6]) + hi_f(a1[6]),
                        bias[7] + lo_f(a1[7]) + hi_f(a1[7]));
        *(float4*)(dst + 64 + 4) = o;

        if (half == 0) {
            CP_WAIT(0);
            __syncthreads();
        }
    }
}

// ---------------------------------------------------------------------------
// Recurrent scan (r8 structure): 2 seqs per 128-thread block, cp.async
// double-buffered pre chunks.
// MODE 0: coalesced natural store g_mid[(b,h)][w][j] (1 wavefront/warp).
// MODE 1: remap store to out[b][j][h][w] (8B groups), r8 exact.
// ---------------------------------------------------------------------------
template <int MODE>
__global__ __launch_bounds__(128, 4) void scan_kernel(const float* __restrict__ Whh,
                                                      float* __restrict__ out) {
    __shared__ float pre_sh[2][2][16][64];   // [buf][sl][tt][j] 16KB
    __shared__ float hbuf[2][2][80];         // pad 80: conflict-free remap

    int tid = threadIdx.x;
    int sl  = tid >> 6;
    int j   = tid & 63;
    int s0  = blockIdx.x * 2;
    int b   = s0 >> 7;
    int p0  = s0 & 127;

    const float* preg = g_pre + (size_t)s0 * 8192;

    ull w2[32];
    {
        const ull* wr = (const ull*)(Whh + j * 64);
        #pragma unroll
        for (int i = 0; i < 32; i++) w2[i] = wr[i];
    }

    hbuf[0][sl][j] = 0.f;

    uint32_t preb = (uint32_t)__cvta_generic_to_shared(&pre_sh[0][0][0][0]);

    // chunk 0
    {
        #pragma unroll
        for (int i = 0; i < 4; i++) {
            int e = tid * 4 + i * 512;
            int seq = e >> 10, off = e & 1023;
            cp_async16(preb + e * 4, preg + (size_t)seq * 8192 + off);
        }
        CP_COMMIT();
    }

    float* outp;
    int j2 = 0, s2 = 0;
    if (MODE == 0) {
        outp = g_mid + (size_t)(s0 + sl) * 8192 + j;                       // + t*64
    } else {
        j2 = tid >> 1;  s2 = tid & 1;
        outp = out + (size_t)b * 1048576 + (size_t)j2 * 16384 + p0 + s2;   // + t*128
    }

    int cur = 0;
    for (int k = 0; k < 8; k++) {
        __syncthreads();
        if (k < 7) {
            int bk = (k + 1) & 1;
            #pragma unroll
            for (int i = 0; i < 4; i++) {
                int e = tid * 4 + i * 512;
                int seq = e >> 10, off = e & 1023;
                cp_async16(preb + (bk * 2048 + e) * 4,
                           preg + (size_t)seq * 8192 + (k + 1) * 1024 + off);
            }
            CP_COMMIT();
            CP_WAIT(1);
        } else {
            CP_WAIT(0);
        }
        __syncthreads();

        const float* pvp = &pre_sh[k & 1][sl][0][j];

        #pragma unroll 4
        for (int tt = 0; tt < 16; tt++) {
            float pv = pvp[tt * 64];

            const ulonglong2* h2 = (const ulonglong2*)hbuf[cur][sl];
            ull a0 = 0, a1 = 0, a2 = 0, a3 = 0;
            #pragma unroll
            for (int i = 0; i < 16; i += 2) {
                ulonglong2 ha = h2[i];
                a0 = ffma2(w2[2 * i],     ha.x, a0);
                a1 = ffma2(w2[2 * i + 1], ha.y, a1);
                ulonglong2 hb = h2[i + 1];
                a2 = ffma2(w2[2 * i + 2], hb.x, a2);
                a3 = ffma2(w2[2 * i + 3], hb.y, a3);
            }
            a0 = addf2(a0, a1);
            a2 = addf2(a2, a3);
            a0 = addf2(a0, a2);
            float s_ = pv + lo_f(a0) + hi_f(a0);
            float hn = tanh_fast(s_);

            int nxt = cur ^ 1;
            hbuf[nxt][sl][j] = hn;
            __syncthreads();

            int t = k * 16 + tt;
            if (MODE == 0) {
                outp[(size_t)t * 64] = hn;          // coalesced 128B/warp
            } else {
                float v = hbuf[nxt][s2][j2];        // conflict-free remap
                outp[(size_t)t * 128] = v;
            }

            cur = nxt;
        }
    }
}

// ---------------------------------------------------------------------------
extern "C" void kernel_launch(void* const* d_in, const int* in_sizes, int n_in,
                              void* d_out, int out_size) {
    const float* x     = (const float*)d_in[0];
    const float* Wih_x = (const float*)d_in[1];
    const float* Whh_x = (const float*)d_in[2];
    const float* bih_x = (const float*)d_in[3];
    const float* bhh_x = (const float*)d_in[4];
    const float* Wih_y = (const float*)d_in[5];
    const float* Whh_y = (const float*)d_in[6];
    const float* bih_y = (const float*)d_in[7];
    const float* bhh_y = (const float*)d_in[8];
    float* out = (float*)d_out;

    prep_kernel<<<1, 256>>>(Wih_x, Wih_y, bih_x, bhh_x, bih_y, bhh_y);
    proj_x_kernel<<<2048, 256>>>(x);                   // pre_x [(b,h)][w][j]
    scan_kernel<0><<<1024, 128>>>(Whh_x, nullptr);     // scan w -> g_mid [(b,h)][w][j]
    proj_y_kernel<<<2048, 256>>>();                    // pre_y [(b,w)][h][j2]
    scan_kernel<1><<<1024, 128>>>(Whh_y, out);         // scan h -> out [b][j][h][w]
}

// round 12
// speedup vs baseline: 1.6294x; 1.6294x over previous
#include <cuda_runtime.h>
#include <cstdint>

// x: [16, 64, 128, 128] (B, C, H, W), HX = HY = 64.
// Pass 1: 2048 sequences (b,h), T=128 along w.
// Pass 2: 2048 sequences (b,w), T=128 along h.

using ull = unsigned long long;

__device__ float g_pre[2048 * 128 * 64];   // [seq][t][j]
__device__ float g_mid[2048 * 128 * 64];   // [(b,h)][w][j]  natural scan_x output
__device__ float g_WTx[64 * 64];           // Wih_x^T: [c][j]
__device__ float g_WTy[64 * 64];           // Wih_y^T: [j][j2]
__device__ ull   g_bsdx[64];               // dup'd bias sums
__device__ ull   g_bsdy[64];

__device__ __forceinline__ ull ffma2(ull a, ull b, ull c) {
    ull d;
    asm("fma.rn.f32x2 %0, %1, %2, %3;" : "=l"(d) : "l"(a), "l"(b), "l"(c));
    return d;
}
__device__ __forceinline__ ull addf2(ull a, ull b) {
    ull d;
    asm("add.rn.f32x2 %0, %1, %2;" : "=l"(d) : "l"(a), "l"(b));
    return d;
}
__device__ __forceinline__ ull dup2(float x) {
    ull d;
    asm("mov.b64 %0, {%1, %1};" : "=l"(d) : "r"(__float_as_uint(x)));
    return d;
}
__device__ __forceinline__ float lo_f(ull v) { return __uint_as_float((unsigned)(v & 0xffffffffull)); }
__device__ __forceinline__ float hi_f(ull v) { return __uint_as_float((unsigned)(v >> 32)); }
__device__ __forceinline__ float tanh_fast(float x) {
    float r;
    asm("tanh.approx.f32 %0, %1;" : "=f"(r) : "f"(x));
    return r;
}
__device__ __forceinline__ void cp_async16(uint32_t dst, const void* src) {
    asm volatile("cp.async.cg.shared.global [%0], [%1], 16;" :: "r"(dst), "l"(src));
}
#define CP_COMMIT() asm volatile("cp.async.commit_group;")
#define CP_WAIT(n)  asm volatile("cp.async.wait_group %0;" :: "n"(n))

// ---------------------------------------------------------------------------
// Prep.
// ---------------------------------------------------------------------------
__global__ void prep_kernel(const float* __restrict__ Wih_x,
                            const float* __restrict__ Wih_y,
                            const float* __restrict__ bih_x,
                            const float* __restrict__ bhh_x,
                            const float* __restrict__ bih_y,
                            const float* __restrict__ bhh_y) {
    int t = threadIdx.x;
    for (int e = t; e < 4096; e += 256) {
        int c = e >> 6, j = e & 63;
        g_WTx[c * 64 + j] = Wih_x[j * 64 + c];
        g_WTy[c * 64 + j] = Wih_y[j * 64 + c];
    }
    if (t < 64) {
        g_bsdx[t] = dup2(bih_x[t] + bhh_x[t]);
        g_bsdy[t] = dup2(bih_y[t] + bhh_y[t]);
    }
}

// ---------------------------------------------------------------------------
// Shared proj compute: pre[row][pos][j] = bias[j] + sum_c in_sh[c][pos]*W_sh[c][j]
// (r8-proven: broadcast X within half-warp, conflict-free W sweep)
// PAD = in_sh row stride in floats (128 for proj_x, 132 for proj_y).
// ---------------------------------------------------------------------------
template <int PAD>
__device__ __forceinline__ void proj_compute(const float in_sh[64][PAD],
                                             const float W_sh[64][64],
                                             const ull* bsd, int tid, int row) {
    int pt = tid >> 4;    // position group of 8 (broadcast X)
    int jt = tid & 15;    // output group of 4 (conflict-free W)

    const ull* bd = bsd + jt * 4;
    ull a[4][4];
    #pragma unroll
    for (int o = 0; o < 4; o++) {
        ull bv = bd[o];
        a[0][o] = bv; a[1][o] = bv; a[2][o] = bv; a[3][o] = bv;
    }

    #pragma unroll 8
    for (int c = 0; c < 64; c++) {
        ulonglong2 X0 = *(const ulonglong2*)&in_sh[c][pt * 8];
        ulonglong2 X1 = *(const ulonglong2*)&in_sh[c][pt * 8 + 4];
        float4 wv = *(const float4*)&W_sh[c][jt * 4];
        ull w0 = dup2(wv.x), w1 = dup2(wv.y), w2 = dup2(wv.z), w3 = dup2(wv.w);
        a[0][0] = ffma2(X0.x, w0, a[0][0]);  a[1][0] = ffma2(X0.y, w0, a[1][0]);
        a[2][0] = ffma2(X1.x, w0, a[2][0]);  a[3][0] = ffma2(X1.y, w0, a[3][0]);
        a[0][1] = ffma2(X0.x, w1, a[0][1]);  a[1][1] = ffma2(X0.y, w1, a[1][1]);
        a[2][1] = ffma2(X1.x, w1, a[2][1]);  a[3][1] = ffma2(X1.y, w1, a[3][1]);
        a[0][2] = ffma2(X0.x, w2, a[0][2]);  a[1][2] = ffma2(X0.y, w2, a[1][2]);
        a[2][2] = ffma2(X1.x, w2, a[2][2]);  a[3][2] = ffma2(X1.y, w2, a[3][2]);
        a[0][3] = ffma2(X0.x, w3, a[0][3]);  a[1][3] = ffma2(X0.y, w3, a[1][3]);
        a[2][3] = ffma2(X1.x, w3, a[2][3]);  a[3][3] = ffma2(X1.y, w3, a[3][3]);
    }

    float* dst = g_pre + (size_t)row * 8192 + (pt * 8) * 64 + jt * 4;
    #pragma unroll
    for (int pp = 0; pp < 4; pp++) {
        float4 o;
        o = make_float4(lo_f(a[pp][0]), lo_f(a[pp][1]), lo_f(a[pp][2]), lo_f(a[pp][3]));
        *(float4*)(dst + (pp * 2 + 0) * 64) = o;
        o = make_float4(hi_f(a[pp][0]), hi_f(a[pp][1]), hi_f(a[pp][2]), hi_f(a[pp][3]));
        *(float4*)(dst + (pp * 2 + 1) * 64) = o;
    }
}

// ---------------------------------------------------------------------------
// proj_x: r8-exact. in = x[b][c][h][w], c-major cp.async staging.
// ---------------------------------------------------------------------------
__global__ __launch_bounds__(256) void proj_x_kernel(const float* __restrict__ src) {
    __shared__ float in_sh[64][128];   // [c][pos]  32KB
    __shared__ float W_sh[64][64];     // [c][j]    16KB

    int tid = threadIdx.x;
    int row = blockIdx.x;
    int b = row >> 7, h = row & 127;
    const float* base = src + (size_t)b * 1048576 + (size_t)h * 128;

    uint32_t shW = (uint32_t)__cvta_generic_to_shared(&W_sh[0][0]);
    uint32_t shI = (uint32_t)__cvta_generic_to_shared(&in_sh[0][0]);
    {
        #pragma unroll
        for (int i = 0; i < 4; i++) {
            int e = tid + i * 256;               // 0..1023
            cp_async16(shW + e * 16, g_WTx + e * 4);
        }
        #pragma unroll
        for (int i = 0; i < 8; i++) {
            int e = tid + i * 256;               // 0..2047, 32 granules/row
            int c = e >> 5, g4 = e & 31;
            cp_async16(shI + e * 16, base + (size_t)c * 16384 + g4 * 4);
        }
        CP_COMMIT();
        CP_WAIT(0);
        __syncthreads();
    }
    proj_compute<128>(in_sh, W_sh, g_bsdx, tid, row);
}

// ---------------------------------------------------------------------------
// proj_y: same compute; input from natural g_mid[(b,h)][w][j] via in-register
// 4x4 tile transpose into in_sh[j][h] (pad 132: aligned STS.128, ~2-way max).
// ---------------------------------------------------------------------------
__global__ __launch_bounds__(256) void proj_y_kernel() {
    __shared__ float in_sh[64][132];   // [j][h]  33.8KB
    __shared__ float W_sh[64][64];     // [j][j2] 16KB

    int tid = threadIdx.x;
    int row = blockIdx.x;              // b*128 + w
    int b = row >> 7, w = row & 127;
    const float* mid_base = g_mid + (size_t)b * 1048576 + (size_t)w * 64;  // + h*8192 + j

    // W via cp.async while we do the LDG transpose
    uint32_t shW = (uint32_t)__cvta_generic_to_shared(&W_sh[0][0]);
    #pragma unroll
    for (int i = 0; i < 4; i++) {
        int e = tid + i * 256;
        cp_async16(shW + e * 16, g_WTy + e * 4);
    }
    CP_COMMIT();

    // Input: 512 tiles of 4h x 4j; 2 tiles/thread. LDG.128 x4 -> transpose -> STS.128 x4
    #pragma unroll
    for (int i = 0; i < 2; i++) {
        int tl = tid + i * 256;                  // 0..511
        int h4 = tl >> 4, j4 = tl & 15;
        const float* p = mid_base + (size_t)(h4 * 4) * 8192 + j4 * 4;
        float4 r0 = *(const float4*)(p + 0 * 8192);
        float4 r1 = *(const float4*)(p + 1 * 8192);
        float4 r2 = *(const float4*)(p + 2 * 8192);
        float4 r3 = *(const float4*)(p + 3 * 8192);
        *(float4*)&in_sh[j4 * 4 + 0][h4 * 4] = make_float4(r0.x, r1.x, r2.x, r3.x);
        *(float4*)&in_sh[j4 * 4 + 1][h4 * 4] = make_float4(r0.y, r1.y, r2.y, r3.y);
        *(float4*)&in_sh[j4 * 4 + 2][h4 * 4] = make_float4(r0.z, r1.z, r2.z, r3.z);
        *(float4*)&in_sh[j4 * 4 + 3][h4 * 4] = make_float4(r0.w, r1.w, r2.w, r3.w);
    }
    CP_WAIT(0);
    __syncthreads();

    proj_compute<132>(in_sh, W_sh, g_bsdy, tid, row);
}

// ---------------------------------------------------------------------------
// Recurrent scan (r8 structure): 2 seqs per 128-thread block, cp.async
// double-buffered pre chunks of 16 steps.
// MODE 0: coalesced natural store g_mid[(b,h)][w][j] (128B/warp/step).
// MODE 1: remap store to out[b][j][h][w] (8B groups), r8 exact.
// ---------------------------------------------------------------------------
template <int MODE>
__global__ __launch_bounds__(128, 4) void scan_kernel(const float* __restrict__ Whh,
                                                      float* __restrict__ out) {
    __shared__ float pre_sh[2][2][16][64];   // [buf][sl][tt][j] 16KB
    __shared__ float hbuf[2][2][80];         // pad 80: conflict-free remap

    int tid = threadIdx.x;
    int sl  = tid >> 6;
    int j   = tid & 63;
    int s0  = blockIdx.x * 2;
    int b   = s0 >> 7;
    int p0  = s0 & 127;

    const float* preg = g_pre + (size_t)s0 * 8192;

    ull w2[32];
    {
        const ull* wr = (const ull*)(Whh + j * 64);
        #pragma unroll
        for (int i = 0; i < 32; i++) w2[i] = wr[i];
    }

    hbuf[0][sl][j] = 0.f;

    uint32_t preb = (uint32_t)__cvta_generic_to_shared(&pre_sh[0][0][0][0]);

    // chunk 0
    {
        #pragma unroll
        for (int i = 0; i < 4; i++) {
            int e = tid * 4 + i * 512;
            int seq = e >> 10, off = e & 1023;
            cp_async16(preb + e * 4, preg + (size_t)seq * 8192 + off);
        }
        CP_COMMIT();
    }

    float* outp;
    int j2 = 0, s2 = 0;
    if (MODE == 0) {
        outp = g_mid + (size_t)(s0 + sl) * 8192 + j;                       // + t*64
    } else {
        j2 = tid >> 1;  s2 = tid & 1;
        outp = out + (size_t)b * 1048576 + (size_t)j2 * 16384 + p0 + s2;   // + t*128
    }

    int cur = 0;
    for (int k = 0; k < 8; k++) {
        __syncthreads();
        if (k < 7) {
            int bk = (k + 1) & 1;
            #pragma unroll
            for (int i = 0; i < 4; i++) {
                int e = tid * 4 + i * 512;
                int seq = e >> 10, off = e & 1023;
                cp_async16(preb + (bk * 2048 + e) * 4,
                           preg + (size_t)seq * 8192 + (k + 1) * 1024 + off);
            }
            CP_COMMIT();
            CP_WAIT(1);
        } else {
            CP_WAIT(0);
        }
        __syncthreads();

        const float* pvp = &pre_sh[k & 1][sl][0][j];

        #pragma unroll 4
        for (int tt = 0; tt < 16; tt++) {
            float pv = pvp[tt * 64];

            const ulonglong2* h2 = (const ulonglong2*)hbuf[cur][sl];
            ull a0 = 0, a1 = 0, a2 = 0, a3 = 0;
            #pragma unroll
            for (int i = 0; i < 16; i += 2) {
                ulonglong2 ha = h2[i];
                a0 = ffma2(w2[2 * i],     ha.x, a0);
                a1 = ffma2(w2[2 * i + 1], ha.y, a1);
                ulonglong2 hb = h2[i + 1];
                a2 = ffma2(w2[2 * i + 2], hb.x, a2);
                a3 = ffma2(w2[2 * i + 3], hb.y, a3);
            }
            a0 = addf2(a0, a1);
            a2 = addf2(a2, a3);
            a0 = addf2(a0, a2);
            float s_ = pv + lo_f(a0) + hi_f(a0);
            float hn = tanh_fast(s_);

            int nxt = cur ^ 1;
            hbuf[nxt][sl][j] = hn;
            __syncthreads();

            int t = k * 16 + tt;
            if (MODE == 0) {
                outp[(size_t)t * 64] = hn;          // fully coalesced
            } else {
                float v = hbuf[nxt][s2][j2];        // conflict-free remap
                outp[(size_t)t * 128] = v;
            }

            cur = nxt;
        }
    }
}

// ---------------------------------------------------------------------------
extern "C" void kernel_launch(void* const* d_in, const int* in_sizes, int n_in,
                              void* d_out, int out_size) {
    const float* x     = (const float*)d_in[0];
    const float* Wih_x = (const float*)d_in[1];
    const float* Whh_x = (const float*)d_in[2];
    const float* bih_x = (const float*)d_in[3];
    const float* bhh_x = (const float*)d_in[4];
    const float* Wih_y = (const float*)d_in[5];
    const float* Whh_y = (const float*)d_in[6];
    const float* bih_y = (const float*)d_in[7];
    const float* bhh_y = (const float*)d_in[8];
    float* out = (float*)d_out;

    prep_kernel<<<1, 256>>>(Wih_x, Wih_y, bih_x, bhh_x, bih_y, bhh_y);
    proj_x_kernel<<<2048, 256>>>(x);                   // pre_x [(b,h)][w][j]
    scan_kernel<0><<<1024, 128>>>(Whh_x, nullptr);     // scan w -> g_mid natural
    proj_y_kernel<<<2048, 256>>>();                    // pre_y [(b,w)][h][j2]
    scan_kernel<1><<<1024, 128>>>(Whh_y, out);         // scan h -> out [b][j][h][w]
}